// round 17
// baseline (speedup 1.0000x reference)
#include <cuda_runtime.h>
#include <cuda_bf16.h>
#include <math.h>
#include <stdint.h>

// Problem constants (fixed shapes from the reference)
#define Bdim 4
#define Hdim 8
#define Tdim 512
#define Ddim 512
#define DhD  64
#define NL   64     // number of lag candidates
#define KTOP 18     // top-k lags = 2*ceil(log2(512)) = 18
#define NSLOT 19    // 1 (lag 0 / instantaneous) + KTOP
#define BH   (Bdim*Hdim)

// lags for T=512, LMAX=64: step=7 -> 1,8,...,442 then last forced to 511
__device__ __forceinline__ int lag_of(int l) { return (l == NL-1) ? (Tdim-1) : (1 + 7*l); }

// ---------------- mma.sync / cp.async helpers --------------------------------
__device__ __forceinline__ uint32_t smem_u32(const void* p) {
    uint32_t a;
    asm("{ .reg .u64 t; cvta.to.shared.u64 t, %1; cvt.u32.u64 %0, t; }" : "=r"(a) : "l"(p));
    return a;
}
__device__ __forceinline__ void ldsm4(uint32_t r[4], uint32_t addr) {
    asm volatile("ldmatrix.sync.aligned.m8n8.x4.shared.b16 {%0,%1,%2,%3}, [%4];"
        : "=r"(r[0]), "=r"(r[1]), "=r"(r[2]), "=r"(r[3]) : "r"(addr));
}
__device__ __forceinline__ void mma16816(float d[4], const uint32_t a[4], const uint32_t b[2]) {
    asm volatile("mma.sync.aligned.m16n8k16.row.col.f32.bf16.bf16.f32 "
        "{%0,%1,%2,%3},{%4,%5,%6,%7},{%8,%9},{%0,%1,%2,%3};"
        : "+f"(d[0]), "+f"(d[1]), "+f"(d[2]), "+f"(d[3])
        : "r"(a[0]), "r"(a[1]), "r"(a[2]), "r"(a[3]), "r"(b[0]), "r"(b[1]));
}
__device__ __forceinline__ void cp_async16(uint32_t smem_addr, const void* gptr) {
    asm volatile("cp.async.cg.shared.global [%0], [%1], 16;"
                 :: "r"(smem_addr), "l"(gptr) : "memory");
}
#define CP_COMMIT() asm volatile("cp.async.commit_group;" ::: "memory")
#define CP_WAIT(n)  asm volatile("cp.async.wait_group %0;" :: "n"(n) : "memory")

// ---------------- pack helper: fp32 -> (hi bf16, lo bf16) u32 ----------------
__device__ __forceinline__ uint32_t pack_hilo(float v) {
    __nv_bfloat16 h = __float2bfloat16(v);
    float hf = __bfloat162float(h);
    __nv_bfloat16 l = __float2bfloat16(v - hf);
    return (uint32_t)(*(unsigned short*)&h) | ((uint32_t)(*(unsigned short*)&l) << 16);
}

// ---------------- scratch (static device memory; no runtime allocation) ----
__device__ float g_Q[BH*Tdim*DhD];                 // 4 MB, raw (pre-norm)
__device__ float g_K[BH*Tdim*DhD];                 // 4 MB, raw (pre-norm)
__device__ uint32_t g_VP[BH*Tdim*DhD];             // 4 MB: V packed (hi,lo), head-major
__device__ uint32_t g_xP[Bdim*Tdim*Ddim];          // 4 MB: x packed (hi,lo), row-major
__device__ uint32_t g_WP[4*Ddim*Ddim];             // 4 MB: W^T packed, z = q,k,v,o
__device__ uint32_t g_oP[Bdim*Tdim*Ddim];          // 4 MB: out_h packed (from contrib)
__device__ uint32_t g_Kph[(size_t)BH*4*DhD*1024];  // 33.5 MB: 4 pre-shift phases, doubled
__device__ uint32_t g_QT[(size_t)BH*DhD*512];      // 4.2 MB: [bh][c][t], (hi,lo) packed
__device__ float g_cov[(size_t)BH*(NL+1)*DhD*DhD]; // 34 MB (slot NL = lag 0)
__device__ float g_score[BH*NL];
__device__ int   g_shift[BH*NSLOT];
__device__ float g_wslot[BH*NSLOT];
__device__ int   g_covsel[BH*NSLOT];
__device__ uint32_t g_attwT[(size_t)BH*NSLOT*DhD*DhD]; // 10 MB: [c][d] packed

// ---------------- prep_xw: pack x (z=4) / transpose+pack weights (z=0..3) ----
__global__ void prep_xw_kernel(const float* __restrict__ x,
                               const float* __restrict__ Wq, const float* __restrict__ Wk,
                               const float* __restrict__ Wv, const float* __restrict__ Wo)
{
    const int z = blockIdx.z;
    const int tid = threadIdx.x;
    if (z < 4) {
        __shared__ uint32_t s[64][65];
        const float* W = (z == 0) ? Wq : (z == 1) ? Wk : (z == 2) ? Wv : Wo;
        uint32_t* dst = g_WP + (size_t)z*Ddim*Ddim;
        const int k0 = blockIdx.x * 64, n0 = blockIdx.y * 64;
        #pragma unroll
        for (int p = tid; p < 4096; p += 256) {
            int r = p >> 6, c = p & 63;   // r: k idx, c: n idx
            s[c][r] = pack_hilo(W[(size_t)(k0 + r)*Ddim + n0 + c]);
        }
        __syncthreads();
        #pragma unroll
        for (int p = tid; p < 4096; p += 256) {
            int n = p >> 6, k = p & 63;
            dst[(size_t)(n0 + n)*Ddim + k0 + k] = s[n][k];
        }
    } else {
        int base = (blockIdx.y*8 + blockIdx.x)*16384 + tid*4;
        #pragma unroll
        for (int i = 0; i < 16; i++) {
            int idx = base + i*1024;
            float4 v = *(const float4*)(x + idx);
            uint4 o;
            o.x = pack_hilo(v.x); o.y = pack_hilo(v.y);
            o.z = pack_hilo(v.z); o.w = pack_hilo(v.w);
            *(uint4*)(g_xP + idx) = o;
        }
    }
}

// ---------------- QKV GEMM via HMMA, M=128 tile, pipelined -------------------
#define CSTRIDE 144
__global__ void __launch_bounds__(256) gemm_qkv_mma(const float* __restrict__ bq,
                                                    const float* __restrict__ bk,
                                                    const float* __restrict__ bv)
{
    __shared__ __align__(16) char sA[128*CSTRIDE];  // 18 KB
    __shared__ __align__(16) char sB[64*CSTRIDE];   // 9 KB
    const int z = blockIdx.z;
    const float* bias = (z == 0) ? bq : (z == 1) ? bk : bv;
    float* C          = (z == 0) ? g_Q : g_K;
    const uint32_t* BP = g_WP + (size_t)z*Ddim*Ddim;
    const int m0 = blockIdx.x * 128, n0 = blockIdx.y * 64;
    const int tid = threadIdx.x, wid = tid >> 5, lane = tid & 31;
    const int rowstrip = wid & 3, colhalf = wid >> 2;
    const int mw = rowstrip * 16;

    float acc[2][4][4] = {};

    const int srowA = tid >> 1, ssegA = tid & 1;
    const int srowB = tid >> 2, ssegB = tid & 3;
    const int arow_ld = mw + (lane & 15), acol_ld = (lane >> 4) * 8;
    const uint32_t sAb = smem_u32(sA), sBb = smem_u32(sB);

    const uint32_t* srcA0 = g_xP + (size_t)(m0 + srowA)*Ddim + ssegA*16;
    const uint32_t* srcB0 = BP + (size_t)(n0 + srowB)*Ddim + ssegB*8;
    uint32_t* dstA = (uint32_t*)(sA + srowA*CSTRIDE) + ssegA*16;
    uint32_t* dstB = (uint32_t*)(sB + srowB*CSTRIDE) + ssegB*8;

    uint4 rA[4], rB[2];
    #pragma unroll
    for (int i = 0; i < 4; i++) rA[i] = *(const uint4*)(srcA0 + 4*i);
    #pragma unroll
    for (int i = 0; i < 2; i++) rB[i] = *(const uint4*)(srcB0 + 4*i);

    for (int chunk = 0; chunk < 16; chunk++) {
        #pragma unroll
        for (int i = 0; i < 4; i++) *(uint4*)(dstA + 4*i) = rA[i];
        #pragma unroll
        for (int i = 0; i < 2; i++) *(uint4*)(dstB + 4*i) = rB[i];
        __syncthreads();
        if (chunk < 15) {
            const uint32_t* srcA = srcA0 + (chunk+1)*32;
            const uint32_t* srcB = srcB0 + (chunk+1)*32;
            #pragma unroll
            for (int i = 0; i < 4; i++) rA[i] = *(const uint4*)(srcA + 4*i);
            #pragma unroll
            for (int i = 0; i < 2; i++) rB[i] = *(const uint4*)(srcB + 4*i);
        }
        #pragma unroll
        for (int ks = 0; ks < 4; ks++) {
            const int k0 = ks * 16;
            uint32_t a0[4], a1[4];
            ldsm4(a0, sAb + arow_ld*CSTRIDE + (k0 + acol_ld)*2);
            ldsm4(a1, sAb + (arow_ld + 64)*CSTRIDE + (k0 + acol_ld)*2);
            #pragma unroll
            for (int jt2 = 0; jt2 < 2; jt2++) {
                const int jt = colhalf*2 + jt2;
                const int brow = 16*jt + (lane >> 4)*8 + (lane & 7);
                const int bcol = k0 + ((lane >> 3) & 1)*8;
                uint32_t b4[4];
                ldsm4(b4, sBb + brow*CSTRIDE + bcol*2);
                mma16816(acc[0][2*jt2],   a0, b4);
                mma16816(acc[0][2*jt2+1], a0, b4 + 2);
                mma16816(acc[1][2*jt2],   a1, b4);
                mma16816(acc[1][2*jt2+1], a1, b4 + 2);
                uint32_t bs[4];
                #pragma unroll
                for (int i = 0; i < 4; i++) bs[i] = __byte_perm(b4[i], 0, 0x1032);
                mma16816(acc[0][2*jt2],   a0, bs);
                mma16816(acc[0][2*jt2+1], a0, bs + 2);
                mma16816(acc[1][2*jt2],   a1, bs);
                mma16816(acc[1][2*jt2+1], a1, bs + 2);
            }
        }
        __syncthreads();
    }

    const int g = lane >> 2, tig = lane & 3;
    #pragma unroll
    for (int s2 = 0; s2 < 2; s2++) {
        #pragma unroll
        for (int j = 0; j < 4; j++) {
            const int c0 = colhalf*32 + 8*j + 2*tig;
            #pragma unroll
            for (int half = 0; half < 2; half++) {
                int m = m0 + 64*s2 + mw + g + 8*half;
                int b = m >> 9, t = m & (Tdim-1);
                #pragma unroll
                for (int e = 0; e < 2; e++) {
                    int n = n0 + c0 + e;
                    int h = n >> 6, c = n & (DhD-1);
                    size_t idx = (((size_t)(b*Hdim + h))*Tdim + t)*DhD + c;
                    float v = acc[s2][j][2*half + e] + bias[n];
                    if (z == 2) g_VP[idx] = pack_hilo(v);
                    else        C[idx] = v;
                }
            }
        }
    }
}

// ---------------- output GEMM via HMMA, M=128 tile, pipelined ----------------
__global__ void __launch_bounds__(256) gemm_out_mma(const float* __restrict__ bo,
                                                    float* __restrict__ out)
{
    __shared__ __align__(16) char sA[128*CSTRIDE];
    __shared__ __align__(16) char sB[64*CSTRIDE];
    const uint32_t* BP = g_WP + (size_t)3*Ddim*Ddim;
    const int m0 = blockIdx.x * 128, n0 = blockIdx.y * 64;
    const int tid = threadIdx.x, wid = tid >> 5, lane = tid & 31;
    const int rowstrip = wid & 3, colhalf = wid >> 2;
    const int mw = rowstrip * 16;

    float acc[2][4][4] = {};

    const int srowA = tid >> 1, ssegA = tid & 1;
    const int srowB = tid >> 2, ssegB = tid & 3;
    const int arow_ld = mw + (lane & 15), acol_ld = (lane >> 4) * 8;
    const uint32_t sAb = smem_u32(sA), sBb = smem_u32(sB);

    const uint32_t* srcA0 = g_oP + (size_t)(m0 + srowA)*Ddim + ssegA*16;
    const uint32_t* srcB0 = BP + (size_t)(n0 + srowB)*Ddim + ssegB*8;
    uint32_t* dstA = (uint32_t*)(sA + srowA*CSTRIDE) + ssegA*16;
    uint32_t* dstB = (uint32_t*)(sB + srowB*CSTRIDE) + ssegB*8;

    uint4 rA[4], rB[2];
    #pragma unroll
    for (int i = 0; i < 4; i++) rA[i] = *(const uint4*)(srcA0 + 4*i);
    #pragma unroll
    for (int i = 0; i < 2; i++) rB[i] = *(const uint4*)(srcB0 + 4*i);

    for (int chunk = 0; chunk < 16; chunk++) {
        #pragma unroll
        for (int i = 0; i < 4; i++) *(uint4*)(dstA + 4*i) = rA[i];
        #pragma unroll
        for (int i = 0; i < 2; i++) *(uint4*)(dstB + 4*i) = rB[i];
        __syncthreads();
        if (chunk < 15) {
            const uint32_t* srcA = srcA0 + (chunk+1)*32;
            const uint32_t* srcB = srcB0 + (chunk+1)*32;
            #pragma unroll
            for (int i = 0; i < 4; i++) rA[i] = *(const uint4*)(srcA + 4*i);
            #pragma unroll
            for (int i = 0; i < 2; i++) rB[i] = *(const uint4*)(srcB + 4*i);
        }
        #pragma unroll
        for (int ks = 0; ks < 4; ks++) {
            const int k0 = ks * 16;
            uint32_t a0[4], a1[4];
            ldsm4(a0, sAb + arow_ld*CSTRIDE + (k0 + acol_ld)*2);
            ldsm4(a1, sAb + (arow_ld + 64)*CSTRIDE + (k0 + acol_ld)*2);
            #pragma unroll
            for (int jt2 = 0; jt2 < 2; jt2++) {
                const int jt = colhalf*2 + jt2;
                const int brow = 16*jt + (lane >> 4)*8 + (lane & 7);
                const int bcol = k0 + ((lane >> 3) & 1)*8;
                uint32_t b4[4];
                ldsm4(b4, sBb + brow*CSTRIDE + bcol*2);
                mma16816(acc[0][2*jt2],   a0, b4);
                mma16816(acc[0][2*jt2+1], a0, b4 + 2);
                mma16816(acc[1][2*jt2],   a1, b4);
                mma16816(acc[1][2*jt2+1], a1, b4 + 2);
                uint32_t bs[4];
                #pragma unroll
                for (int i = 0; i < 4; i++) bs[i] = __byte_perm(b4[i], 0, 0x1032);
                mma16816(acc[0][2*jt2],   a0, bs);
                mma16816(acc[0][2*jt2+1], a0, bs + 2);
                mma16816(acc[1][2*jt2],   a1, bs);
                mma16816(acc[1][2*jt2+1], a1, bs + 2);
            }
        }
        __syncthreads();
    }

    const int g = lane >> 2, tig = lane & 3;
    #pragma unroll
    for (int s2 = 0; s2 < 2; s2++) {
        #pragma unroll
        for (int j = 0; j < 4; j++) {
            const int c0 = colhalf*32 + 8*j + 2*tig;
            const int n = n0 + c0;
            const int r0 = m0 + 64*s2 + mw + g, r1 = r0 + 8;
            *(float2*)(out + (size_t)r0*Ddim + n) =
                make_float2(acc[s2][j][0] + bo[n], acc[s2][j][1] + bo[n+1]);
            *(float2*)(out + (size_t)r1*Ddim + n) =
                make_float2(acc[s2][j][2] + bo[n], acc[s2][j][3] + bo[n+1]);
        }
    }
}

// ---------------- prep_qk: fused sumsq + normalize + transpose + pack --------
__global__ void prep_qk_kernel()
{
    __shared__ float part[256];
    __shared__ float sinv[DhD];
    __shared__ uint32_t s[64][65];
    const int bh = blockIdx.x, t0 = blockIdx.y * 64, isK = blockIdx.z;
    const float* src = (isK ? g_K : g_Q) + (size_t)bh*Tdim*DhD;
    const int tid = threadIdx.x;
    const int d = tid & 63, g = tid >> 6;
    float ss = 0.f;
    for (int t = g*128; t < (g+1)*128; t++) {
        float v = src[t*DhD + d]; ss = fmaf(v, v, ss);
    }
    part[tid] = ss;
    __syncthreads();
    if (tid < 64) {
        float tot = part[d] + part[d+64] + part[d+128] + part[d+192];
        sinv[d] = 1.0f / sqrtf(fmaxf(tot, 1e-8f));
    }
    __syncthreads();
    #pragma unroll
    for (int p = tid; p < 4096; p += 256) {
        int r = p >> 6, dd = p & 63;
        s[dd][r] = pack_hilo(src[(t0 + r)*DhD + dd] * sinv[dd]);
    }
    __syncthreads();
    if (!isK) {
        uint32_t* dst = g_QT + (size_t)bh*DhD*512;
        #pragma unroll
        for (int p = tid; p < 4096; p += 256) {
            int dd = p >> 6, t = p & 63;
            dst[(size_t)dd*512 + t0 + t] = s[dd][t];
        }
    } else {
        uint32_t* dst = g_Kph + (size_t)bh*4*DhD*1024;
        #pragma unroll
        for (int ph = 0; ph < 4; ph++) {
            for (int p = tid; p < 4096; p += 256) {
                int dd = p >> 6, t = p & 63;
                uint32_t w = s[dd][t];
                int tp = (t0 + t - ph) & (Tdim - 1);
                uint32_t* row = dst + ((size_t)ph*DhD + dd)*1024;
                row[tp]       = w;
                row[tp + 512] = w;
            }
        }
    }
}

// ---------------- cov via HMMA: 4 slots/block, cp.async double-buffered ------
// Dynamic smem: sA[2][256*CSTRIDE] + sB[2][64*CSTRIDE] = 90 KB.
#define COV_SMEM (2*256*CSTRIDE + 2*64*CSTRIDE)
__global__ void __launch_bounds__(256, 2) cov_mma_kernel(const float* __restrict__ lam_ptr)
{
    extern __shared__ __align__(16) char dyn[];
    __shared__ float s_tot[8][2], s_dia[8][2];

    const int quad = blockIdx.x, bh = blockIdx.y;   // slots 4*quad..4*quad+3
    const int tid = threadIdx.x, wid = tid >> 5, lane = tid & 31;
    const int mw = wid * 16;

    float acc[2][8][4] = {};

    // A staging: warp wid stages rows [32*wid, 32*wid+32) -> slot quadrant wid>>1
    const int slotq = wid >> 1;
    const int slotIdA = 4*quad + slotq;
    const int lagA = (slotIdA >= NL) ? 0 : lag_of(slotIdA);
    const int phA = (Tdim - lagA) & 3;
    const int aseg = lane & 7;
    const uint32_t* KBase = g_Kph + ((size_t)bh*4 + phA)*DhD*1024;

    // B staging
    const int srowB = tid >> 2, ssegB = tid & 3;
    const uint32_t* QTr = g_QT + ((size_t)bh*DhD + srowB)*512;

    const int arow_ld = mw + (lane & 15), acol_ld = (lane >> 4) * 8;
    const uint32_t dynb = smem_u32(dyn);
    const uint32_t sAbuf[2] = { dynb, dynb + 256*CSTRIDE };
    const uint32_t sBbuf[2] = { dynb + 2*256*CSTRIDE, dynb + 2*256*CSTRIDE + 64*CSTRIDE };

    // stage chunk t0 into buffer bi
    auto stage = [&](int t0, int bi) {
        const uint32_t dB = sBbuf[bi] + srowB*CSTRIDE + ssegB*32;
        const uint32_t* srcB = QTr + t0 + ssegB*8;
        cp_async16(dB,      srcB);
        cp_async16(dB + 16, srcB + 4);
        const int st = (t0 - lagA + Tdim) & (Tdim - 1);
        const uint32_t* srcA0 = KBase + (st - phA) + aseg*4;
        #pragma unroll
        for (int p = 0; p < 8; p++) {
            const int row = wid*32 + p*4 + (lane >> 3);
            const int dA = row & 63;
            cp_async16(sAbuf[bi] + row*CSTRIDE + aseg*16, srcA0 + (size_t)dA*1024);
        }
        CP_COMMIT();
    };

    stage(0, 0);
    for (int chunk = 0; chunk < 16; chunk++) {
        if (chunk < 15) { stage((chunk+1)*32, (chunk+1)&1); CP_WAIT(1); }
        else            { CP_WAIT(0); }
        __syncthreads();
        const uint32_t sAb = sAbuf[chunk & 1], sBb = sBbuf[chunk & 1];
        #pragma unroll
        for (int ks = 0; ks < 4; ks++) {
            const int k0 = ks * 16;
            uint32_t a0[4], a1[4];
            ldsm4(a0, sAb + arow_ld*CSTRIDE + (k0 + acol_ld)*2);
            ldsm4(a1, sAb + (arow_ld + 128)*CSTRIDE + (k0 + acol_ld)*2);
            #pragma unroll
            for (int jt = 0; jt < 4; jt++) {
                const int brow = 16*jt + (lane >> 4)*8 + (lane & 7);
                const int bcol = k0 + ((lane >> 3) & 1)*8;
                uint32_t b4[4];
                ldsm4(b4, sBb + brow*CSTRIDE + bcol*2);
                mma16816(acc[0][2*jt],   a0, b4);
                mma16816(acc[0][2*jt+1], a0, b4 + 2);
                mma16816(acc[1][2*jt],   a1, b4);
                mma16816(acc[1][2*jt+1], a1, b4 + 2);
                uint32_t bs[4];
                #pragma unroll
                for (int i = 0; i < 4; i++) bs[i] = __byte_perm(b4[i], 0, 0x1032);
                mma16816(acc[0][2*jt],   a0, bs);
                mma16816(acc[0][2*jt+1], a0, bs + 2);
                mma16816(acc[1][2*jt],   a1, bs);
                mma16816(acc[1][2*jt+1], a1, bs + 2);
            }
        }
        __syncthreads();
    }

    const int g = lane >> 2, tig = lane & 3;
    #pragma unroll
    for (int grp = 0; grp < 2; grp++) {
        const int grow = mw + 128*grp;
        const int slot = 4*quad + (grow >> 6);
        const int d0 = (grow & 63) + g, d1 = d0 + 8;
        float tot = 0.f, dia = 0.f;
        if (slot <= NL) {
            float* covp = g_cov + ((size_t)bh*(NL+1) + slot)*(DhD*DhD);
            #pragma unroll
            for (int j = 0; j < 8; j++) {
                const int c0 = 8*j + 2*tig;
                *(float2*)(covp + d0*DhD + c0) = make_float2(acc[grp][j][0], acc[grp][j][1]);
                *(float2*)(covp + d1*DhD + c0) = make_float2(acc[grp][j][2], acc[grp][j][3]);
                tot += fabsf(acc[grp][j][0]) + fabsf(acc[grp][j][1])
                     + fabsf(acc[grp][j][2]) + fabsf(acc[grp][j][3]);
                if (d0 == c0)     dia += fabsf(acc[grp][j][0]);
                if (d0 == c0 + 1) dia += fabsf(acc[grp][j][1]);
                if (d1 == c0)     dia += fabsf(acc[grp][j][2]);
                if (d1 == c0 + 1) dia += fabsf(acc[grp][j][3]);
            }
        }
        #pragma unroll
        for (int o = 16; o > 0; o >>= 1) {
            tot += __shfl_xor_sync(0xffffffffu, tot, o);
            dia += __shfl_xor_sync(0xffffffffu, dia, o);
        }
        if (lane == 0) { s_tot[wid][grp] = tot; s_dia[wid][grp] = dia; }
    }
    __syncthreads();
    if (tid < 4) {
        const int slot = 4*quad + tid;
        if (slot < NL) {
            const int grp = tid >> 1, wbase = (tid & 1)*4;
            float T = 0.f, D = 0.f;
            #pragma unroll
            for (int i = 0; i < 4; i++) { T += s_tot[wbase+i][grp]; D += s_dia[wbase+i][grp]; }
            float lam = fminf(fmaxf(*lam_ptr, 0.f), 1.f);
            g_score[bh*NL + slot] = lam*D + (1.f - lam)*(T - D);
        }
    }
}

// ---------------- top-18 lag selection: one warp per bh, shuffle argmax ------
__global__ void topk_kernel(const float* __restrict__ lt_lag,
                            const float* __restrict__ beta_ptr)
{
    const int bh = blockIdx.x, l = threadIdx.x; // 32 threads
    float v0 = g_score[bh*NL + l];
    float v1 = g_score[bh*NL + l + 32];
    float selV[KTOP]; int selI[KTOP];
    #pragma unroll
    for (int k = 0; k < KTOP; k++) {
        float bv; int bi;
        if (v0 >= v1) { bv = v0; bi = l; } else { bv = v1; bi = l + 32; }
        #pragma unroll
        for (int o = 16; o > 0; o >>= 1) {
            float ov = __shfl_xor_sync(0xffffffffu, bv, o);
            int   oi = __shfl_xor_sync(0xffffffffu, bi, o);
            if (ov > bv || (ov == bv && oi < bi)) { bv = ov; bi = oi; }
        }
        selV[k] = bv; selI[k] = bi;
        if (bi == l)      v0 = -3.4e38f;
        if (bi == l + 32) v1 = -3.4e38f;
    }
    if (l == 0) {
        float tl = fmaxf(expf(*lt_lag), 1e-4f);
        float mx = selV[0];
        float e[KTOP], esum = 0.f;
        #pragma unroll
        for (int k = 0; k < KTOP; k++) { e[k] = expf((selV[k] - mx)/tl); esum += e[k]; }
        float beta = fminf(fmaxf(*beta_ptr, 0.f), 1.f);
        g_shift[bh*NSLOT]  = 0;
        g_wslot[bh*NSLOT]  = 1.f - beta;
        g_covsel[bh*NSLOT] = NL;
        #pragma unroll
        for (int k = 0; k < KTOP; k++) {
            g_shift[bh*NSLOT + 1 + k]  = lag_of(selI[k]);
            g_wslot[bh*NSLOT + 1 + k]  = beta * e[k] / esum;
            g_covsel[bh*NSLOT + 1 + k] = selI[k];
        }
    }
}

// ---------------- attwT[s][c][d] = pack(weight_s * softmax_c(cov/tau)) -------
__global__ void att_kernel(const float* __restrict__ log_tau_ptr)
{
    __shared__ uint32_t sT[64][65];
    const int s = blockIdx.x, bh = blockIdx.y;
    const int l = g_covsel[bh*NSLOT + s];
    const float w = g_wslot[bh*NSLOT + s];
    const float invtau = 1.0f / fmaxf(expf(*log_tau_ptr), 1e-4f);
    const float* covp = g_cov + ((size_t)bh*(NL+1) + l)*(DhD*DhD);
    uint32_t* outp = g_attwT + ((size_t)bh*NSLOT + s)*(DhD*DhD);
    const int tid = threadIdx.x;
    int warp = tid >> 5, lane = tid & 31;
    for (int d = warp; d < DhD; d += 8) {
        float v0 = covp[d*DhD + lane]      * invtau;
        float v1 = covp[d*DhD + lane + 32] * invtau;
        float m = fmaxf(v0, v1);
        #pragma unroll
        for (int o = 16; o > 0; o >>= 1) m = fmaxf(m, __shfl_xor_sync(0xffffffffu, m, o));
        float e0 = expf(v0 - m), e1 = expf(v1 - m);
        float ss = e0 + e1;
        #pragma unroll
        for (int o = 16; o > 0; o >>= 1) ss += __shfl_xor_sync(0xffffffffu, ss, o);
        float f = w / ss;
        sT[lane][d]      = pack_hilo(e0 * f);
        sT[lane + 32][d] = pack_hilo(e1 * f);
    }
    __syncthreads();
    #pragma unroll
    for (int p = tid; p < 4096; p += 256) {
        outp[p] = sT[p >> 6][p & 63];
    }
}

// ---------------- contrib via HMMA, M=128 t-tile, pipelined ------------------
__global__ void __launch_bounds__(256) contrib_mma_kernel()
{
    __shared__ __align__(16) char sA[128*CSTRIDE];
    __shared__ __align__(16) char sB[64*CSTRIDE];
    const int bh = blockIdx.y, t0 = blockIdx.x * 128;
    const int bb = bh >> 3, hh = bh & 7;
    const int tid = threadIdx.x, wid = tid >> 5, lane = tid & 31;
    const int rowstrip = wid & 3, colhalf = wid >> 2;
    const int mw = rowstrip * 16;

    float acc[2][4][4] = {};

    const int srowA = tid >> 1, ssegA = tid & 1;
    const int srowB = tid >> 2, ssegB = tid & 3;
    const int arow_ld = mw + (lane & 15), acol_ld = (lane >> 4) * 8;
    const uint32_t sAb = smem_u32(sA), sBb = smem_u32(sB);

    const uint32_t* VPb = g_VP + (size_t)bh*Tdim*DhD;
    uint32_t* dstA = (uint32_t*)(sA + srowA*CSTRIDE) + ssegA*16;
    uint32_t* dstB = (uint32_t*)(sB + srowB*CSTRIDE) + ssegB*8;

    uint4 rA[4], rB[2];
    {
        const int shift = g_shift[bh*NSLOT];
        const uint32_t* ap = g_attwT + (size_t)bh*NSLOT*(DhD*DhD);
        const int srcT = (t0 + srowA - shift + Tdim) & (Tdim - 1);
        const uint32_t* srcA = VPb + (size_t)srcT*DhD + ssegA*16;
        const uint32_t* srcB = ap + srowB*DhD + ssegB*8;
        #pragma unroll
        for (int i = 0; i < 4; i++) rA[i] = *(const uint4*)(srcA + 4*i);
        #pragma unroll
        for (int i = 0; i < 2; i++) rB[i] = *(const uint4*)(srcB + 4*i);
    }

    for (int it = 0; it < NSLOT*2; it++) {
        #pragma unroll
        for (int i = 0; i < 4; i++) *(uint4*)(dstA + 4*i) = rA[i];
        #pragma unroll
        for (int i = 0; i < 2; i++) *(uint4*)(dstB + 4*i) = rB[i];
        __syncthreads();
        if (it < NSLOT*2 - 1) {
            const int nit = it + 1;
            const int s = nit >> 1, kh = nit & 1;
            const int shift = g_shift[bh*NSLOT + s];
            const uint32_t* ap = g_attwT + ((size_t)bh*NSLOT + s)*(DhD*DhD);
            const int srcT = (t0 + srowA - shift + Tdim) & (Tdim - 1);
            const uint32_t* srcA = VPb + (size_t)srcT*DhD + kh*32 + ssegA*16;
            const uint32_t* srcB = ap + srowB*DhD + kh*32 + ssegB*8;
            #pragma unroll
            for (int i = 0; i < 4; i++) rA[i] = *(const uint4*)(srcA + 4*i);
            #pragma unroll
            for (int i = 0; i < 2; i++) rB[i] = *(const uint4*)(srcB + 4*i);
        }
        #pragma unroll
        for (int ks = 0; ks < 4; ks++) {
            const int k0 = ks * 16;
            uint32_t a0[4], a1[4];
            ldsm4(a0, sAb + arow_ld*CSTRIDE + (k0 + acol_ld)*2);
            ldsm4(a1, sAb + (arow_ld + 64)*CSTRIDE + (k0 + acol_ld)*2);
            #pragma unroll
            for (int jt2 = 0; jt2 < 2; jt2++) {
                const int jt = colhalf*2 + jt2;
                const int brow = 16*jt + (lane >> 4)*8 + (lane & 7);
                const int bcol = k0 + ((lane >> 3) & 1)*8;
                uint32_t b4[4];
                ldsm4(b4, sBb + brow*CSTRIDE + bcol*2);
                mma16816(acc[0][2*jt2],   a0, b4);
                mma16816(acc[0][2*jt2+1], a0, b4 + 2);
                mma16816(acc[1][2*jt2],   a1, b4);
                mma16816(acc[1][2*jt2+1], a1, b4 + 2);
                uint32_t bs[4];
                #pragma unroll
                for (int i = 0; i < 4; i++) bs[i] = __byte_perm(b4[i], 0, 0x1032);
                mma16816(acc[0][2*jt2],   a0, bs);
                mma16816(acc[0][2*jt2+1], a0, bs + 2);
                mma16816(acc[1][2*jt2],   a1, bs);
                mma16816(acc[1][2*jt2+1], a1, bs + 2);
            }
        }
        __syncthreads();
    }

    const int g = lane >> 2, tig = lane & 3;
    #pragma unroll
    for (int s2 = 0; s2 < 2; s2++) {
        #pragma unroll
        for (int j = 0; j < 4; j++) {
            const int c0 = colhalf*32 + 8*j + 2*tig;
            #pragma unroll
            for (int half = 0; half < 2; half++) {
                int t = t0 + 64*s2 + mw + g + 8*half;
                size_t row = ((size_t)(bb*Tdim + t))*Ddim + hh*DhD;
                g_oP[row + c0]     = pack_hilo(acc[s2][j][2*half + 0]);
                g_oP[row + c0 + 1] = pack_hilo(acc[s2][j][2*half + 1]);
            }
        }
    }
}

// ---------------- launch ------------------------------------------------------
extern "C" void kernel_launch(void* const* d_in, const int* in_sizes, int n_in,
                              void* d_out, int out_size)
{
    const float* x           = (const float*)d_in[0];
    const float* Wq          = (const float*)d_in[1];
    const float* bq          = (const float*)d_in[2];
    const float* Wk          = (const float*)d_in[3];
    const float* bk          = (const float*)d_in[4];
    const float* Wv          = (const float*)d_in[5];
    const float* bv          = (const float*)d_in[6];
    const float* Wo          = (const float*)d_in[7];
    const float* bo          = (const float*)d_in[8];
    const float* log_tau     = (const float*)d_in[9];
    const float* lambda_auto = (const float*)d_in[10];
    const float* beta_lag    = (const float*)d_in[11];
    const float* log_tau_lag = (const float*)d_in[12];
    float* out = (float*)d_out;

    // Host-side attribute set (not a stream op; capture-safe; idempotent).
    cudaFuncSetAttribute(cov_mma_kernel,
                         cudaFuncAttributeMaxDynamicSharedMemorySize, COV_SMEM);

    prep_xw_kernel<<<dim3(8, 8, 5), 256>>>(x, Wq, Wk, Wv, Wo);
    gemm_qkv_mma<<<dim3(Bdim*Tdim/128, Ddim/64, 3), 256>>>(bq, bk, bv);
    prep_qk_kernel<<<dim3(BH, 8, 2), 256>>>();
    cov_mma_kernel<<<dim3(17, BH), 256, COV_SMEM>>>(lambda_auto);
    topk_kernel<<<BH, 32>>>(log_tau_lag, beta_lag);
    att_kernel<<<dim3(NSLOT, BH), 256>>>(log_tau);
    contrib_mma_kernel<<<dim3(Tdim/128, BH), 256>>>();
    gemm_out_mma<<<dim3(Bdim*Tdim/128, Ddim/64), 256>>>(bo, out);
}